// round 14
// baseline (speedup 1.0000x reference)
#include <cuda_runtime.h>
#include <cstdint>
#include <cstddef>

// ---------------------------------------------------------------------------
// LlamaDecoderLayer fp32. GEMMs + attention via portable mma.sync tf32.
// B operands stream directly from original W[K,N]. 128x128 CTA tiles,
// 3 CTAs/SM for wave balance. T=2048, D=2048, NH=32, NKV=8, HD=64, FF=8192.
// ---------------------------------------------------------------------------

#define T_LEN 2048
#define DMODEL 2048
#define NHEAD 32
#define NKV 8
#define HD 64
#define FF 8192
#define QKV_N 3072

// ---- scratch -------------------------------------------------------------
__device__ float g_xn  [T_LEN * DMODEL];     // h1 exact (residual)
__device__ float g_xnt [T_LEN * DMODEL];     // h1 tf32-rounded (GEMM A)
__device__ float g_qkv [T_LEN * QKV_N];
__device__ float g_att [T_LEN * DMODEL];     // attention out, tf32-rounded
__device__ float g_h2  [T_LEN * DMODEL];
__device__ float g_h3  [T_LEN * DMODEL];     // exact (residual)
__device__ float g_h3t [T_LEN * DMODEL];     // rounded (GEMM A)
__device__ float g_gate[T_LEN * FF];         // h3t @ wg (raw)
__device__ float g_gb  [T_LEN * FF];         // silu(gate)*up, rounded
__device__ float g_rt  [T_LEN * 64];         // rope table: (cos,sin) x 32 per row

// ---------------------------------------------------------------------------
// helpers
// ---------------------------------------------------------------------------
__device__ __forceinline__ uint32_t smem_u32(const void* p) {
    uint32_t a;
    asm("{ .reg .u64 t; cvta.to.shared.u64 t, %1; cvt.u32.u64 %0, t; }" : "=r"(a) : "l"(p));
    return a;
}
__device__ __forceinline__ float to_tf32(float x) {
    asm("cvt.rna.tf32.f32 %0, %1;" : "=f"(x) : "f"(x));
    return x;
}
#define CP16(sm_addr, gptr) \
    asm volatile("cp.async.cg.shared.global [%0], [%1], 16;" :: "r"(sm_addr), "l"(gptr))
#define CP_COMMIT() asm volatile("cp.async.commit_group;")
#define CP_WAIT1()  asm volatile("cp.async.wait_group 1;")

__device__ __forceinline__ void mma_f(float* c, const float* a, const float* b) {
    asm volatile("mma.sync.aligned.m16n8k8.row.col.f32.tf32.tf32.f32 "
                 "{%0,%1,%2,%3}, {%4,%5,%6,%7}, {%8,%9}, {%0,%1,%2,%3};"
                 : "+f"(c[0]), "+f"(c[1]), "+f"(c[2]), "+f"(c[3])
                 : "r"(__float_as_uint(a[0])), "r"(__float_as_uint(a[1])),
                   "r"(__float_as_uint(a[2])), "r"(__float_as_uint(a[3])),
                   "r"(__float_as_uint(b[0])), "r"(__float_as_uint(b[1])));
}
__device__ __forceinline__ void mma_u(float* c, const uint32_t* a, const float* b) {
    asm volatile("mma.sync.aligned.m16n8k8.row.col.f32.tf32.tf32.f32 "
                 "{%0,%1,%2,%3}, {%4,%5,%6,%7}, {%8,%9}, {%0,%1,%2,%3};"
                 : "+f"(c[0]), "+f"(c[1]), "+f"(c[2]), "+f"(c[3])
                 : "r"(a[0]), "r"(a[1]), "r"(a[2]), "r"(a[3]),
                   "r"(__float_as_uint(b[0])), "r"(__float_as_uint(b[1])));
}

// ---------------------------------------------------------------------------
// rope table: row t, d=0..31 -> (cos, sin)
// ---------------------------------------------------------------------------
__global__ __launch_bounds__(256) void rope_table_k(float* __restrict__ rt)
{
    int i = blockIdx.x * blockDim.x + threadIdx.x;   // over T*32
    int t = i >> 5, d = i & 31;
    double freq = exp((double)(-2.0 * d / 64.0) * 9.210340371976184);
    double si, co;
    sincos(freq * (double)t, &si, &co);
    ((float2*)rt)[i] = make_float2((float)co, (float)si);
}

// ---------------------------------------------------------------------------
// tf32 tensor-core GEMM: CTA 128x128, 4 warps x (64x64), BK=16, 3-stage,
// 3 CTAs/SM. Warp-level math identical to the 128x256 version (bit-identical
// outputs). C[M,Nc] = A[M,K] @ Wsel[K,*] (+add0 +add1). epi: 0=none,1=rope,2=silu.
// ---------------------------------------------------------------------------
#define ASTRIDE 20
#define BSTRIDE 136
#define A_BYTES (128 * ASTRIDE * 4)          // 10240
#define B_BYTES (16 * BSTRIDE * 4)           // 8704
#define STG_B   (A_BYTES + B_BYTES)          // 18944
#define GSM_TOTAL (3 * STG_B)                // 56832

__global__ __launch_bounds__(128, 3) void tgemm_k(const float* __restrict__ A,
                                                  const float* __restrict__ B0,
                                                  const float* __restrict__ B1,
                                                  const float* __restrict__ B2,
                                                  float* __restrict__ C,
                                                  int M, int Nc, int K,
                                                  int sB0, int sB1, int sB2,
                                                  int blk1, int blk2,
                                                  const float* __restrict__ add0,
                                                  const float* __restrict__ add1,
                                                  int epi,
                                                  const float* __restrict__ epi_src)
{
    extern __shared__ char sm[];
    const uint32_t smb = smem_u32(sm);
    const int tid = threadIdx.x;
    const int wid = tid >> 5, lane = tid & 31;
    const int warp_m = wid & 1;          // 0..1 -> 64-row half
    const int warp_n = wid >> 1;         // 0..1 -> 64-col half
    const int bx = blockIdx.x;
    const int brow = blockIdx.y * 128;
    const int bcol = bx * 128;

    const float* B; int strideB, bcolB;
    if (bx < blk1)      { B = B0; strideB = sB0; bcolB = bx * 128; }
    else if (bx < blk2) { B = B1; strideB = sB1; bcolB = (bx - blk1) * 128; }
    else                { B = B2; strideB = sB2; bcolB = (bx - blk2) * 128; }

    // A loader: thread t -> row t, 16 cols, 4x CP16
    const float* aG = A + (size_t)(brow + tid) * K;
    const uint32_t sA0 = smb + tid * (ASTRIDE * 4);
    // B loader: thread t -> k-row t>>3, col chunk (t&7)*16, 4x CP16
    const int bkr = tid >> 3, bc = (tid & 7) * 16;
    const float* bG = B + (size_t)bkr * strideB + bcolB + bc;
    const uint32_t sB0a = smb + A_BYTES + (bkr * BSTRIDE + bc) * 4;

    float c[4][8][4];
    #pragma unroll
    for (int mi = 0; mi < 4; mi++)
        #pragma unroll
        for (int ni = 0; ni < 8; ni++)
            #pragma unroll
            for (int j = 0; j < 4; j++) c[mi][ni][j] = 0.f;

    const int nk = K >> 4;

    #pragma unroll
    for (int p = 0; p < 2; p++) {
        const float* a0 = aG + p * 16;
        const float* b0 = bG + (size_t)p * 16 * strideB;
        uint32_t sa = sA0 + p * STG_B;
        uint32_t sb = sB0a + p * STG_B;
        #pragma unroll
        for (int j = 0; j < 4; j++) CP16(sa + j * 16, a0 + j * 4);
        #pragma unroll
        for (int j = 0; j < 4; j++) CP16(sb + j * 16, b0 + j * 4);
        CP_COMMIT();
    }

    const int r1 = lane >> 2, cq = lane & 3;
    const uint32_t lm_off =
        ((uint32_t)(warp_m * 64 + ((lane >> 3) & 1) * 8 + (lane & 7)) * ASTRIDE
         + (uint32_t)(lane >> 4) * 4) * 4;

    for (int kt = 0; kt < nk; kt++) {
        CP_WAIT1();
        __syncthreads();

        if (kt + 2 < nk) {
            int st = (kt + 2) % 3;
            const float* a0 = aG + (size_t)(kt + 2) * 16;
            const float* b0 = bG + (size_t)(kt + 2) * 16 * strideB;
            uint32_t sa = sA0 + st * STG_B;
            uint32_t sb = sB0a + st * STG_B;
            #pragma unroll
            for (int j = 0; j < 4; j++) CP16(sa + j * 16, a0 + j * 4);
            #pragma unroll
            for (int j = 0; j < 4; j++) CP16(sb + j * 16, b0 + j * 4);
        }
        CP_COMMIT();

        const uint32_t stg = smb + (kt % 3) * STG_B;
        const float* Bs = (const float*)(sm + (kt % 3) * STG_B + A_BYTES);

        #pragma unroll
        for (int kk = 0; kk < 2; kk++) {
            uint32_t a[4][4];
            float b[8][2];
            const uint32_t abase = stg + lm_off + kk * 32;
            #pragma unroll
            for (int mi = 0; mi < 4; mi++) {
                asm volatile("ldmatrix.sync.aligned.m8n8.x4.shared.b16 {%0,%1,%2,%3}, [%4];"
                             : "=r"(a[mi][0]), "=r"(a[mi][1]),
                               "=r"(a[mi][2]), "=r"(a[mi][3])
                             : "r"(abase + (uint32_t)(mi * 16 * ASTRIDE * 4)));
            }
            const float* bp = Bs + (kk * 8 + cq) * BSTRIDE + warp_n * 64 + r1;
            #pragma unroll
            for (int ni = 0; ni < 8; ni++) {
                b[ni][0] = bp[ni * 8];
                b[ni][1] = bp[4 * BSTRIDE + ni * 8];
            }
            #pragma unroll
            for (int mi = 0; mi < 4; mi++)
                #pragma unroll
                for (int ni = 0; ni < 8; ni++)
                    mma_u(c[mi][ni], a[mi], b[ni]);
        }
    }

    // ---- epilogue ----
    #pragma unroll
    for (int mi = 0; mi < 4; mi++) {
        #pragma unroll
        for (int part = 0; part < 2; part++) {
            int r = brow + warp_m * 64 + mi * 16 + r1 + part * 8;
            size_t rowbase = (size_t)r * Nc;
            #pragma unroll
            for (int ni = 0; ni < 8; ni++) {
                int col = bcol + warp_n * 64 + ni * 8 + cq * 2;
                float2 v = make_float2(c[mi][ni][part * 2], c[mi][ni][part * 2 + 1]);
                if (epi == 1) {
                    if (col < 2560) {   // rope on q (0..2047) and k (2048..2559)
                        int dp = (col & 63) >> 1;
                        float2 cssn = ((const float2*)epi_src)[r * 32 + dp];
                        float x1 = v.x, x2 = v.y;
                        v.x = x1 * cssn.x - x2 * cssn.y;
                        v.y = x2 * cssn.x + x1 * cssn.y;
                    }
                } else if (epi == 2) {  // v = up; combine with gate
                    const float2 gt = *(const float2*)&epi_src[rowbase + col];
                    v.x = to_tf32(gt.x / (1.f + __expf(-gt.x)) * v.x);
                    v.y = to_tf32(gt.y / (1.f + __expf(-gt.y)) * v.y);
                }
                if (add0) { const float2 a2 = *(const float2*)&add0[rowbase + col];
                            v.x += a2.x; v.y += a2.y; }
                if (add1) { const float2 a2 = *(const float2*)&add1[rowbase + col];
                            v.x += a2.x; v.y += a2.y; }
                *(float2*)&C[rowbase + col] = v;
            }
        }
    }
}

// ---------------------------------------------------------------------------
// Tensor-core flash attention (causal GQA) — R10 version (known 205us).
// ---------------------------------------------------------------------------
#define ATT_SMEM_FLOATS (4352 + 4352 + 4608 + 4352)
#define ATT_SMEM_BYTES  (ATT_SMEM_FLOATS * 4)

__global__ __launch_bounds__(128) void attn_tc_k(const float* __restrict__ QKV,
                                                 float* __restrict__ Oa)
{
    extern __shared__ float s[];
    float* qsm = s;                  // [64][68]
    float* ksm = s + 4352;           // [64][68]
    float* vsm = s + 8704;           // [64][72]
    float* psm = s + 13312;          // [4][16][68]

    const int tid = threadIdx.x;
    const int w = tid >> 5, lane = tid & 31;
    const int r1 = lane >> 2, cq = lane & 3;
    const int qt = blockIdx.x, h = blockIdx.y;
    const int kvh = h >> 2;

    {
        const float* qb = QKV + (size_t)(qt * 64) * QKV_N + h * HD;
        for (int t = tid; t < 1024; t += 128) {
            int i = t >> 4, d4 = (t & 15) * 4;
            float4 v4 = *(const float4*)(qb + (size_t)i * QKV_N + d4);
            v4.x = to_tf32(v4.x); v4.y = to_tf32(v4.y);
            v4.z = to_tf32(v4.z); v4.w = to_tf32(v4.w);
            *(float4*)(qsm + i * 68 + d4) = v4;
        }
    }
    __syncthreads();

    float qf[8][4];
    {
        const float* qb = qsm + (w * 16 + r1) * 68 + cq;
        #pragma unroll
        for (int ks = 0; ks < 8; ks++) {
            qf[ks][0] = qb[ks * 8];
            qf[ks][1] = qb[8 * 68 + ks * 8];
            qf[ks][2] = qb[ks * 8 + 4];
            qf[ks][3] = qb[8 * 68 + ks * 8 + 4];
        }
    }

    float oA[8][4];
    #pragma unroll
    for (int nt = 0; nt < 8; nt++)
        #pragma unroll
        for (int j = 0; j < 4; j++) oA[nt][j] = 0.f;
    float m0 = -1e30f, m1 = -1e30f, l0 = 0.f, l1 = 0.f;

    float* pb = psm + w * 16 * 68;

    for (int jt = 0; jt <= qt; jt++) {
        __syncthreads();
        {
            const float* kb = QKV + (size_t)(jt * 64) * QKV_N + DMODEL + kvh * HD;
            const float* vb = kb + 512;
            for (int t = tid; t < 1024; t += 128) {
                int i = t >> 4, d4 = (t & 15) * 4;
                float4 k4 = *(const float4*)(kb + (size_t)i * QKV_N + d4);
                k4.x = to_tf32(k4.x); k4.y = to_tf32(k4.y);
                k4.z = to_tf32(k4.z); k4.w = to_tf32(k4.w);
                *(float4*)(ksm + i * 68 + d4) = k4;
                float4 v4 = *(const float4*)(vb + (size_t)i * QKV_N + d4);
                v4.x = to_tf32(v4.x); v4.y = to_tf32(v4.y);
                v4.z = to_tf32(v4.z); v4.w = to_tf32(v4.w);
                *(float4*)(vsm + i * 72 + d4) = v4;
            }
        }
        __syncthreads();

        float sA[8][4];
        #pragma unroll
        for (int nt = 0; nt < 8; nt++) {
            float acc[4] = {0.f, 0.f, 0.f, 0.f};
            const float* kbp = ksm + (nt * 8 + r1) * 68 + cq;
            #pragma unroll
            for (int ks = 0; ks < 8; ks++) {
                float bf[2] = { kbp[ks * 8], kbp[ks * 8 + 4] };
                mma_f(acc, qf[ks], bf);
            }
            sA[nt][0] = acc[0]; sA[nt][1] = acc[1];
            sA[nt][2] = acc[2]; sA[nt][3] = acc[3];
        }

        float mn0 = m0, mn1 = m1;
        const int row0 = w * 16 + r1, row1 = row0 + 8;
        #pragma unroll
        for (int nt = 0; nt < 8; nt++) {
            #pragma unroll
            for (int j = 0; j < 4; j++) sA[nt][j] *= 0.125f;
            if (jt == qt) {
                int colb = nt * 8 + 2 * cq;
                if (colb     > row0) sA[nt][0] = -1e30f;
                if (colb + 1 > row0) sA[nt][1] = -1e30f;
                if (colb     > row1) sA[nt][2] = -1e30f;
                if (colb + 1 > row1) sA[nt][3] = -1e30f;
            }
            mn0 = fmaxf(mn0, fmaxf(sA[nt][0], sA[nt][1]));
            mn1 = fmaxf(mn1, fmaxf(sA[nt][2], sA[nt][3]));
        }
        mn0 = fmaxf(mn0, __shfl_xor_sync(0xffffffffu, mn0, 1));
        mn0 = fmaxf(mn0, __shfl_xor_sync(0xffffffffu, mn0, 2));
        mn1 = fmaxf(mn1, __shfl_xor_sync(0xffffffffu, mn1, 1));
        mn1 = fmaxf(mn1, __shfl_xor_sync(0xffffffffu, mn1, 2));

        float c0 = __expf(m0 - mn0), c1 = __expf(m1 - mn1);
        m0 = mn0; m1 = mn1;

        float ls0 = 0.f, ls1 = 0.f;
        #pragma unroll
        for (int nt = 0; nt < 8; nt++) {
            float p0 = to_tf32(__expf(sA[nt][0] - mn0));
            float p1 = to_tf32(__expf(sA[nt][1] - mn0));
            float p2 = to_tf32(__expf(sA[nt][2] - mn1));
            float p3 = to_tf32(__expf(sA[nt][3] - mn1));
            ls0 += p0 + p1; ls1 += p2 + p3;
            int cb = nt * 8 + 2 * cq;
            pb[r1 * 68 + cb]       = p0;
            pb[r1 * 68 + cb + 1]   = p1;
            pb[(r1 + 8) * 68 + cb]     = p2;
            pb[(r1 + 8) * 68 + cb + 1] = p3;
        }
        ls0 += __shfl_xor_sync(0xffffffffu, ls0, 1);
        ls0 += __shfl_xor_sync(0xffffffffu, ls0, 2);
        ls1 += __shfl_xor_sync(0xffffffffu, ls1, 1);
        ls1 += __shfl_xor_sync(0xffffffffu, ls1, 2);
        l0 = l0 * c0 + ls0;
        l1 = l1 * c1 + ls1;

        #pragma unroll
        for (int nt = 0; nt < 8; nt++) {
            oA[nt][0] *= c0; oA[nt][1] *= c0;
            oA[nt][2] *= c1; oA[nt][3] *= c1;
        }
        __syncwarp();

        #pragma unroll
        for (int ks = 0; ks < 8; ks++) {
            float af[4];
            af[0] = pb[r1 * 68 + ks * 8 + cq];
            af[1] = pb[(r1 + 8) * 68 + ks * 8 + cq];
            af[2] = pb[r1 * 68 + ks * 8 + cq + 4];
            af[3] = pb[(r1 + 8) * 68 + ks * 8 + cq + 4];
            const float* vb0 = vsm + (ks * 8 + cq) * 72 + r1;
            const float* vb1 = vsm + (ks * 8 + cq + 4) * 72 + r1;
            #pragma unroll
            for (int nt = 0; nt < 8; nt++) {
                float bf[2] = { vb0[nt * 8], vb1[nt * 8] };
                mma_f(oA[nt], af, bf);
            }
        }
    }

    float inv0 = 1.f / l0, inv1 = 1.f / l1;
    int gr0 = qt * 64 + w * 16 + r1;
    #pragma unroll
    for (int nt = 0; nt < 8; nt++) {
        int col = h * HD + nt * 8 + 2 * cq;
        float2 v0 = make_float2(to_tf32(oA[nt][0] * inv0), to_tf32(oA[nt][1] * inv0));
        float2 v1 = make_float2(to_tf32(oA[nt][2] * inv1), to_tf32(oA[nt][3] * inv1));
        *(float2*)&Oa[(size_t)gr0 * DMODEL + col] = v0;
        *(float2*)&Oa[(size_t)(gr0 + 8) * DMODEL + col] = v1;
    }
}

// ---------------------------------------------------------------------------
// RMSNorm: out exact, outT tf32-rounded
// ---------------------------------------------------------------------------
__global__ __launch_bounds__(256) void rmsnorm_k(const float* __restrict__ x,
                                                 const float* __restrict__ g,
                                                 float* __restrict__ out,
                                                 float* __restrict__ outT)
{
    int row = blockIdx.x;
    int tid = threadIdx.x;
    const float4* xr4 = (const float4*)(x + (size_t)row * DMODEL);
    const float4* g4  = (const float4*)g;

    float4 a = xr4[tid];
    float4 b = xr4[tid + 256];
    float s = a.x*a.x + a.y*a.y + a.z*a.z + a.w*a.w
            + b.x*b.x + b.y*b.y + b.z*b.z + b.w*b.w;
    #pragma unroll
    for (int off = 16; off > 0; off >>= 1) s += __shfl_xor_sync(0xffffffffu, s, off);

    __shared__ float red[8];
    __shared__ float inv_s;
    int wid = tid >> 5, lane = tid & 31;
    if (lane == 0) red[wid] = s;
    __syncthreads();
    if (tid == 0) {
        float t = 0.f;
        #pragma unroll
        for (int w = 0; w < 8; w++) t += red[w];
        inv_s = rsqrtf(t / (float)DMODEL + 1e-5f);
    }
    __syncthreads();
    float inv = inv_s;

    float4 ga = g4[tid], gb = g4[tid + 256];
    float4 ra, rb;
    ra.x = a.x*ga.x*inv; ra.y = a.y*ga.y*inv; ra.z = a.z*ga.z*inv; ra.w = a.w*ga.w*inv;
    rb.x = b.x*gb.x*inv; rb.y = b.y*gb.y*inv; rb.z = b.z*gb.z*inv; rb.w = b.w*gb.w*inv;
    ((float4*)(out + (size_t)row * DMODEL))[tid] = ra;
    ((float4*)(out + (size_t)row * DMODEL))[tid + 256] = rb;
    if (outT) {
        float4 ta = make_float4(to_tf32(ra.x), to_tf32(ra.y), to_tf32(ra.z), to_tf32(ra.w));
        float4 tb = make_float4(to_tf32(rb.x), to_tf32(rb.y), to_tf32(rb.z), to_tf32(rb.w));
        ((float4*)(outT + (size_t)row * DMODEL))[tid] = ta;
        ((float4*)(outT + (size_t)row * DMODEL))[tid + 256] = tb;
    }
}

// ---------------------------------------------------------------------------
// kernel_launch
// ---------------------------------------------------------------------------
extern "C" void kernel_launch(void* const* d_in, const int* in_sizes, int n_in,
                              void* d_out, int out_size)
{
    (void)in_sizes; (void)n_in; (void)out_size;
    const float* x  = (const float*)d_in[0];
    const float* g1 = (const float*)d_in[1];
    const float* wq = (const float*)d_in[2];
    const float* wk = (const float*)d_in[3];
    const float* wv = (const float*)d_in[4];
    const float* wo = (const float*)d_in[5];
    const float* g2 = (const float*)d_in[6];
    const float* wg = (const float*)d_in[7];
    const float* wu = (const float*)d_in[8];
    const float* wd = (const float*)d_in[9];
    float* out = (float*)d_out;

    float *xn, *xnt, *qkv, *att, *h2, *h3, *h3t, *gate, *gb, *rt;
    cudaGetSymbolAddress((void**)&xn,   g_xn);
    cudaGetSymbolAddress((void**)&xnt,  g_xnt);
    cudaGetSymbolAddress((void**)&qkv,  g_qkv);
    cudaGetSymbolAddress((void**)&att,  g_att);
    cudaGetSymbolAddress((void**)&h2,   g_h2);
    cudaGetSymbolAddress((void**)&h3,   g_h3);
    cudaGetSymbolAddress((void**)&h3t,  g_h3t);
    cudaGetSymbolAddress((void**)&gate, g_gate);
    cudaGetSymbolAddress((void**)&gb,   g_gb);
    cudaGetSymbolAddress((void**)&rt,   g_rt);

    cudaFuncSetAttribute(tgemm_k,   cudaFuncAttributeMaxDynamicSharedMemorySize, GSM_TOTAL);
    cudaFuncSetAttribute(attn_tc_k, cudaFuncAttributeMaxDynamicSharedMemorySize, ATT_SMEM_BYTES);

    // rope table + h1 = rmsnorm(x, g1)
    rope_table_k<<<T_LEN * 32 / 256, 256>>>(rt);
    rmsnorm_k<<<T_LEN, 256>>>(x, g1, xn, xnt);

    // qkv = h1t @ [wq|wk|wv], rope fused into epilogue  (384 tiles)
    tgemm_k<<<dim3(QKV_N/128, T_LEN/128), 128, GSM_TOTAL>>>(
        xnt, wq, wk, wv, qkv, T_LEN, QKV_N, DMODEL,
        DMODEL, 512, 512, 16, 20, nullptr, nullptr, 1, rt);

    attn_tc_k<<<dim3(T_LEN/64, NHEAD), 128, ATT_SMEM_BYTES>>>(qkv, att);

    // h2 = h1 + att @ wo  (256 tiles)
    tgemm_k<<<dim3(DMODEL/128, T_LEN/128), 128, GSM_TOTAL>>>(
        att, wo, wo, wo, h2, T_LEN, DMODEL, DMODEL,
        DMODEL, DMODEL, DMODEL, 9999, 9999, xn, nullptr, 0, nullptr);

    rmsnorm_k<<<T_LEN, 256>>>(h2, g2, h3, h3t);

    // gate = h3t @ wg  (1024 tiles)
    tgemm_k<<<dim3(FF/128, T_LEN/128), 128, GSM_TOTAL>>>(
        h3t, wg, wg, wg, gate, T_LEN, FF, DMODEL,
        FF, FF, FF, 9999, 9999, nullptr, nullptr, 0, nullptr);

    // gb = tf32(silu(gate) * (h3t @ wu))  (1024 tiles, silu fused)
    tgemm_k<<<dim3(FF/128, T_LEN/128), 128, GSM_TOTAL>>>(
        h3t, wu, wu, wu, gb, T_LEN, FF, DMODEL,
        FF, FF, FF, 9999, 9999, nullptr, nullptr, 2, gate);

    // out = gb @ wd + h3 + x  (256 tiles)
    tgemm_k<<<dim3(DMODEL/128, T_LEN/128), 128, GSM_TOTAL>>>(
        gb, wd, wd, wd, out, T_LEN, DMODEL, FF,
        DMODEL, DMODEL, DMODEL, 9999, 9999, h3, x, 0, nullptr);
}

// round 15
// speedup vs baseline: 1.7787x; 1.7787x over previous
#include <cuda_runtime.h>
#include <cuda_fp16.h>
#include <cstdint>
#include <cstddef>

// ---------------------------------------------------------------------------
// LlamaDecoderLayer fp32. GEMMs via mma.sync m16n8k16 fp16 (fp32 accum),
// attention via mma.sync tf32. Weights pre-transposed+converted to half
// WT[N][K] each launch. T=2048, D=2048, NH=32, NKV=8, HD=64, FF=8192.
// ---------------------------------------------------------------------------

#define T_LEN 2048
#define DMODEL 2048
#define NHEAD 32
#define NKV 8
#define HD 64
#define FF 8192
#define QKV_N 3072

// ---- scratch -------------------------------------------------------------
__device__ float  g_xn  [T_LEN * DMODEL];      // h1 exact (residual)
__device__ float  g_qkv [T_LEN * QKV_N];
__device__ float  g_h2  [T_LEN * DMODEL];
__device__ float  g_h3  [T_LEN * DMODEL];      // exact (residual)
__device__ float  g_gate[T_LEN * FF];          // h3h @ wg (raw fp32)
__device__ float  g_rt  [T_LEN * 64];          // rope table
__device__ __half g_xnh [T_LEN * DMODEL];      // h1, half (GEMM A)
__device__ __half g_h3h [T_LEN * DMODEL];      // h3, half (GEMM A)
__device__ __half g_atth[T_LEN * DMODEL];      // attention out, half
__device__ __half g_gbh [T_LEN * FF];          // silu(gate)*up, half
// transposed half weights: WT[n][k] = (half)W[k][n]
__device__ __half g_wqkvT[QKV_N * DMODEL];
__device__ __half g_woT  [DMODEL * DMODEL];
__device__ __half g_wguT [2 * FF * DMODEL];
__device__ __half g_wdT  [DMODEL * FF];

// ---------------------------------------------------------------------------
// helpers
// ---------------------------------------------------------------------------
__device__ __forceinline__ uint32_t smem_u32(const void* p) {
    uint32_t a;
    asm("{ .reg .u64 t; cvta.to.shared.u64 t, %1; cvt.u32.u64 %0, t; }" : "=r"(a) : "l"(p));
    return a;
}
__device__ __forceinline__ float to_tf32(float x) {
    asm("cvt.rna.tf32.f32 %0, %1;" : "=f"(x) : "f"(x));
    return x;
}
#define CP16(sm_addr, gptr) \
    asm volatile("cp.async.cg.shared.global [%0], [%1], 16;" :: "r"(sm_addr), "l"(gptr))
#define CP_COMMIT() asm volatile("cp.async.commit_group;")
#define CP_WAIT1()  asm volatile("cp.async.wait_group 1;")

// fp16 mma, fp32 accumulate
__device__ __forceinline__ void mma_h(float* c, const uint32_t* a, uint32_t b0, uint32_t b1) {
    asm volatile("mma.sync.aligned.m16n8k16.row.col.f32.f16.f16.f32 "
                 "{%0,%1,%2,%3}, {%4,%5,%6,%7}, {%8,%9}, {%0,%1,%2,%3};"
                 : "+f"(c[0]), "+f"(c[1]), "+f"(c[2]), "+f"(c[3])
                 : "r"(a[0]), "r"(a[1]), "r"(a[2]), "r"(a[3]), "r"(b0), "r"(b1));
}
// tf32 mma (attention)
__device__ __forceinline__ void mma_f(float* c, const float* a, const float* b) {
    asm volatile("mma.sync.aligned.m16n8k8.row.col.f32.tf32.tf32.f32 "
                 "{%0,%1,%2,%3}, {%4,%5,%6,%7}, {%8,%9}, {%0,%1,%2,%3};"
                 : "+f"(c[0]), "+f"(c[1]), "+f"(c[2]), "+f"(c[3])
                 : "r"(__float_as_uint(a[0])), "r"(__float_as_uint(a[1])),
                   "r"(__float_as_uint(a[2])), "r"(__float_as_uint(a[3])),
                   "r"(__float_as_uint(b[0])), "r"(__float_as_uint(b[1])));
}

// ---------------------------------------------------------------------------
// rope table: row t, d=0..31 -> (cos, sin)
// ---------------------------------------------------------------------------
__global__ __launch_bounds__(256) void rope_table_k(float* __restrict__ rt)
{
    int i = blockIdx.x * blockDim.x + threadIdx.x;
    int t = i >> 5, d = i & 31;
    double freq = exp((double)(-2.0 * d / 64.0) * 9.210340371976184);
    double si, co;
    sincos(freq * (double)t, &si, &co);
    ((float2*)rt)[i] = make_float2((float)co, (float)si);
}

// ---------------------------------------------------------------------------
// Weight transpose + half convert: W[K,N] fp32 -> WT[N,K] half
// ---------------------------------------------------------------------------
__global__ __launch_bounds__(256) void transpose_h_k(const float* __restrict__ W,
                                                     __half* __restrict__ WT,
                                                     int K, int N)
{
    __shared__ float t[32][33];
    int n0 = blockIdx.x * 32, k0 = blockIdx.y * 32;
    int tx = threadIdx.x, ty = threadIdx.y;
    #pragma unroll
    for (int i = 0; i < 32; i += 8)
        t[ty + i][tx] = W[(size_t)(k0 + ty + i) * N + n0 + tx];
    __syncthreads();
    #pragma unroll
    for (int i = 0; i < 32; i += 8)
        WT[(size_t)(n0 + ty + i) * K + k0 + tx] = __float2half_rn(t[tx][ty + i]);
}

// ---------------------------------------------------------------------------
// fp16 tensor-core GEMM: C[M,Nc] = A[M,K] @ WT[N,K]^T (+add0 +add1)
// A half [M][K], WT half [N][K]. CTA 128x256, BK=16, 3-stage cp.async,
// 8 warps x (64x64). epi: 0=none, 1=rope(C fp32), 2=silu(C half, epi_src=gate)
// ---------------------------------------------------------------------------
#define AS 24                                   // halfs per A smem row (16+8)
#define A_BYTES (128 * AS * 2)                  // 6144
#define B_BYTES (256 * AS * 2)                  // 12288
#define STG_B   (A_BYTES + B_BYTES)             // 18432
#define GSM_TOTAL (3 * STG_B)                   // 55296

__global__ __launch_bounds__(256, 1) void tgemm_k(const __half* __restrict__ A,
                                                  const __half* __restrict__ BT,
                                                  void* __restrict__ Cv,
                                                  int M, int Nc, int K,
                                                  const float* __restrict__ add0,
                                                  const float* __restrict__ add1,
                                                  int epi,
                                                  const float* __restrict__ epi_src)
{
    extern __shared__ char sm[];
    const uint32_t smb = smem_u32(sm);
    const int tid = threadIdx.x;
    const int wid = tid >> 5, lane = tid & 31;
    const int warp_m = wid & 1;
    const int warp_n = wid >> 1;
    const int brow = blockIdx.y * 128;
    const int bcol = blockIdx.x * 256;

    // A loader: thread t -> row t>>1, 16B chunk (t&1)   (1x CP16)
    const __half* aG = A + (size_t)(brow + (tid >> 1)) * K + (tid & 1) * 8;
    const uint32_t sA0 = smb + (tid >> 1) * (AS * 2) + (tid & 1) * 16;
    // B loader: thread t -> rows t>>1 and t>>1+128, chunk (t&1)  (2x CP16)
    const __half* bG = BT + (size_t)(bcol + (tid >> 1)) * K + (tid & 1) * 8;
    const uint32_t sB0 = smb + A_BYTES + (tid >> 1) * (AS * 2) + (tid & 1) * 16;
    const size_t bRowStride = (size_t)128 * K;          // +128 rows
    const uint32_t sBRow = 128 * (AS * 2);

    float c[4][8][4];
    #pragma unroll
    for (int mi = 0; mi < 4; mi++)
        #pragma unroll
        for (int ni = 0; ni < 8; ni++)
            #pragma unroll
            for (int j = 0; j < 4; j++) c[mi][ni][j] = 0.f;

    const int nk = K >> 4;

    #pragma unroll
    for (int p = 0; p < 2; p++) {
        const __half* a0 = aG + p * 16;
        const __half* b0 = bG + p * 16;
        uint32_t sa = sA0 + p * STG_B;
        uint32_t sb = sB0 + p * STG_B;
        CP16(sa, a0);
        CP16(sb, b0);
        CP16(sb + sBRow, b0 + bRowStride);
        CP_COMMIT();
    }

    const int r1 = lane >> 2, cq = lane & 3;
    // ldmatrix lane offset (bytes): rows (lane&15), k-half select (lane>>4)
    const uint32_t lm_off =
        (uint32_t)(warp_m * 64 + (lane & 15)) * (AS * 2) + (uint32_t)(lane >> 4) * 16;

    for (int kt = 0; kt < nk; kt++) {
        CP_WAIT1();
        __syncthreads();

        if (kt + 2 < nk) {
            int st = (kt + 2) % 3;
            const __half* a0 = aG + (size_t)(kt + 2) * 16;
            const __half* b0 = bG + (size_t)(kt + 2) * 16;
            uint32_t sa = sA0 + st * STG_B;
            uint32_t sb = sB0 + st * STG_B;
            CP16(sa, a0);
            CP16(sb, b0);
            CP16(sb + sBRow, b0 + bRowStride);
        }
        CP_COMMIT();

        const uint32_t stg = smb + (kt % 3) * STG_B;
        const __half* Bs = (const __half*)(sm + (kt % 3) * STG_B + A_BYTES);

        uint32_t a[4][4];
        const uint32_t abase = stg + lm_off;
        #pragma unroll
        for (int mi = 0; mi < 4; mi++) {
            asm volatile("ldmatrix.sync.aligned.m8n8.x4.shared.b16 {%0,%1,%2,%3}, [%4];"
                         : "=r"(a[mi][0]), "=r"(a[mi][1]),
                           "=r"(a[mi][2]), "=r"(a[mi][3])
                         : "r"(abase + (uint32_t)(mi * 16 * AS * 2)));
        }
        const __half* bp = Bs + (warp_n * 64 + r1) * AS + 2 * cq;
        uint32_t b0[8], b1[8];
        #pragma unroll
        for (int ni = 0; ni < 8; ni++) {
            b0[ni] = *(const uint32_t*)(bp + ni * 8 * AS);
            b1[ni] = *(const uint32_t*)(bp + ni * 8 * AS + 8);
        }
        #pragma unroll
        for (int mi = 0; mi < 4; mi++)
            #pragma unroll
            for (int ni = 0; ni < 8; ni++)
                mma_h(c[mi][ni], a[mi], b0[ni], b1[ni]);
    }

    // ---- epilogue ----
    float* C = (float*)Cv;
    __half* Ch = (__half*)Cv;
    #pragma unroll
    for (int mi = 0; mi < 4; mi++) {
        #pragma unroll
        for (int part = 0; part < 2; part++) {
            int r = brow + warp_m * 64 + mi * 16 + r1 + part * 8;
            size_t rowbase = (size_t)r * Nc;
            #pragma unroll
            for (int ni = 0; ni < 8; ni++) {
                int col = bcol + warp_n * 64 + ni * 8 + cq * 2;
                float2 v = make_float2(c[mi][ni][part * 2], c[mi][ni][part * 2 + 1]);
                if (epi == 1) {
                    if (col < 2560) {   // rope on q (0..2047) and k (2048..2559)
                        int dp = (col & 63) >> 1;
                        float2 cssn = ((const float2*)epi_src)[r * 32 + dp];
                        float x1 = v.x, x2 = v.y;
                        v.x = x1 * cssn.x - x2 * cssn.y;
                        v.y = x2 * cssn.x + x1 * cssn.y;
                    }
                } else if (epi == 2) {  // v = up; silu(gate)*up -> half C
                    const float2 gt = *(const float2*)&epi_src[rowbase + col];
                    float sx = gt.x / (1.f + __expf(-gt.x)) * v.x;
                    float sy = gt.y / (1.f + __expf(-gt.y)) * v.y;
                    *(__half2*)(Ch + rowbase + col) = __floats2half2_rn(sx, sy);
                    continue;
                }
                if (add0) { const float2 a2 = *(const float2*)&add0[rowbase + col];
                            v.x += a2.x; v.y += a2.y; }
                if (add1) { const float2 a2 = *(const float2*)&add1[rowbase + col];
                            v.x += a2.x; v.y += a2.y; }
                *(float2*)&C[rowbase + col] = v;
            }
        }
    }
}

// ---------------------------------------------------------------------------
// Tensor-core flash attention (causal GQA) — R10 version; output half.
// ---------------------------------------------------------------------------
#define ATT_SMEM_FLOATS (4352 + 4352 + 4608 + 4352)
#define ATT_SMEM_BYTES  (ATT_SMEM_FLOATS * 4)

__global__ __launch_bounds__(128) void attn_tc_k(const float* __restrict__ QKV,
                                                 __half* __restrict__ Oa)
{
    extern __shared__ float s[];
    float* qsm = s;                  // [64][68]
    float* ksm = s + 4352;           // [64][68]
    float* vsm = s + 8704;           // [64][72]
    float* psm = s + 13312;          // [4][16][68]

    const int tid = threadIdx.x;
    const int w = tid >> 5, lane = tid & 31;
    const int r1 = lane >> 2, cq = lane & 3;
    const int qt = blockIdx.x, h = blockIdx.y;
    const int kvh = h >> 2;

    {
        const float* qb = QKV + (size_t)(qt * 64) * QKV_N + h * HD;
        for (int t = tid; t < 1024; t += 128) {
            int i = t >> 4, d4 = (t & 15) * 4;
            float4 v4 = *(const float4*)(qb + (size_t)i * QKV_N + d4);
            v4.x = to_tf32(v4.x); v4.y = to_tf32(v4.y);
            v4.z = to_tf32(v4.z); v4.w = to_tf32(v4.w);
            *(float4*)(qsm + i * 68 + d4) = v4;
        }
    }
    __syncthreads();

    float qf[8][4];
    {
        const float* qb = qsm + (w * 16 + r1) * 68 + cq;
        #pragma unroll
        for (int ks = 0; ks < 8; ks++) {
            qf[ks][0] = qb[ks * 8];
            qf[ks][1] = qb[8 * 68 + ks * 8];
            qf[ks][2] = qb[ks * 8 + 4];
            qf[ks][3] = qb[8 * 68 + ks * 8 + 4];
        }
    }

    float oA[8][4];
    #pragma unroll
    for (int nt = 0; nt < 8; nt++)
        #pragma unroll
        for (int j = 0; j < 4; j++) oA[nt][j] = 0.f;
    float m0 = -1e30f, m1 = -1e30f, l0 = 0.f, l1 = 0.f;

    float* pb = psm + w * 16 * 68;

    for (int jt = 0; jt <= qt; jt++) {
        __syncthreads();
        {
            const float* kb = QKV + (size_t)(jt * 64) * QKV_N + DMODEL + kvh * HD;
            const float* vb = kb + 512;
            for (int t = tid; t < 1024; t += 128) {
                int i = t >> 4, d4 = (t & 15) * 4;
                float4 k4 = *(const float4*)(kb + (size_t)i * QKV_N + d4);
                k4.x = to_tf32(k4.x); k4.y = to_tf32(k4.y);
                k4.z = to_tf32(k4.z); k4.w = to_tf32(k4.w);
                *(float4*)(ksm + i * 68 + d4) = k4;
                float4 v4 = *(const float4*)(vb + (size_t)i * QKV_N + d4);
                v4.x = to_tf32(v4.x); v4.y = to_tf32(v4.y);
                v4.z = to_tf32(v4.z); v4.w = to_tf32(v4.w);
                *(float4*)(vsm + i * 72 + d4) = v4;
            }
        }
        __syncthreads();

        float sA[8][4];
        #pragma unroll
        for (int nt = 0; nt < 8; nt++) {
            float acc[4] = {0.f, 0.f, 0.f, 0.f};
            const float* kbp = ksm + (nt * 8 + r1) * 68 + cq;
            #pragma unroll
            for (int ks = 0; ks < 8; ks++) {
                float bf[2] = { kbp[ks * 8], kbp[ks * 8 + 4] };
                mma_f(acc, qf[ks], bf);
            }
            sA[nt][0] = acc[0]; sA[nt][1] = acc[1];
            sA[nt][2] = acc[2]; sA[nt][3] = acc[3];
        }

        float mn0 = m0, mn1 = m1;
        const int row0 = w * 16 + r1, row1 = row0 + 8;
        #pragma unroll
        for (int nt = 0; nt < 8; nt++) {
            #pragma unroll
            for (int j = 0; j < 4; j++) sA[nt][j] *= 0.125f;
            if (jt == qt) {
                int colb = nt * 8 + 2 * cq;
                if (colb     > row0) sA[nt][0] = -1e30f;
                if (colb + 1 > row0) sA[nt][1] = -1e30f;
                if (colb     > row1) sA[nt][2] = -1e30f;
                if (colb + 1 > row1) sA[nt][3] = -1e30f;
            }
            mn0 = fmaxf(mn0, fmaxf(sA[nt][0], sA[nt][1]));
            mn1 = fmaxf(mn1, fmaxf(sA[nt][2], sA[nt][3]));
        }
        mn0 = fmaxf(mn0, __shfl_xor_sync(0xffffffffu, mn0, 1));
        mn0 = fmaxf(mn0, __shfl_xor_sync(0xffffffffu, mn0, 2));
        mn1 = fmaxf(mn1, __shfl_xor_sync(0xffffffffu, mn1, 1));
        mn1 = fmaxf(mn1, __shfl_xor_sync(0xffffffffu, mn1, 2));

        float c0 = __expf(m0 - mn0), c1 = __expf(m1 - mn1);
        m0 = mn0; m1 = mn1;

        float ls0 = 0.f, ls1 = 0.f;
        #pragma unroll
        for (int nt = 0; nt < 8; nt++) {
            float p0 = to_tf32(__expf(sA[nt][0] - mn0));
            float p1 = to_tf32(__expf(sA[nt][1] - mn0));
            float p2 = to_tf32(__expf(sA[nt][2] - mn1));
            float p3 = to_tf32(__expf(sA[nt][3] - mn1));
            ls0 += p0 + p1; ls1 += p2 + p3;
            int cb = nt * 8 + 2 * cq;
            pb[r1 * 68 + cb]       = p0;
            pb[r1 * 68 + cb + 1]   = p1;
            pb[(r1 + 8) * 68 + cb]     = p2;
            pb[(r1 + 8) * 68 + cb + 1] = p3;
        }
        ls0 += __shfl_xor_sync(0xffffffffu, ls0, 1);
        ls0 += __shfl_xor_sync(0xffffffffu, ls0, 2);
        ls1 += __shfl_xor_sync(0xffffffffu, ls1, 1);
        ls1 += __shfl_xor_sync(0xffffffffu, ls1, 2);
        l0 = l0 * c0 + ls0;
        l1 = l1 * c1 + ls1;

        #pragma unroll
        for (int nt = 0; nt < 8; nt++) {
            oA[nt][0] *= c0; oA[nt][1] *= c0;
            oA[nt][2] *= c1; oA[nt][3] *= c1;
        }
        __syncwarp();

        #pragma unroll
        for (int ks = 0; ks < 8; ks++) {
            float af[4];
            af[0] = pb[r1 * 68 + ks * 8 + cq];
            af[1] = pb[(r1 + 8) * 68 + ks * 8 + cq];
            af[2] = pb[r1 * 68 + ks * 8 + cq + 4];
            af[3] = pb[(r1 + 8) * 68 + ks * 8 + cq + 4];
            const float* vb0 = vsm + (ks * 8 + cq) * 72 + r1;
            const float* vb1 = vsm + (ks * 8 + cq + 4) * 72 + r1;
            #pragma unroll
            for (int nt = 0; nt < 8; nt++) {
                float bf[2] = { vb0[nt * 8], vb1[nt * 8] };
                mma_f(oA[nt], af, bf);
            }
        }
    }

    float inv0 = 1.f / l0, inv1 = 1.f / l1;
    int gr0 = qt * 64 + w * 16 + r1;
    #pragma unroll
    for (int nt = 0; nt < 8; nt++) {
        int col = h * HD + nt * 8 + 2 * cq;
        *(__half2*)&Oa[(size_t)gr0 * DMODEL + col] =
            __floats2half2_rn(oA[nt][0] * inv0, oA[nt][1] * inv0);
        *(__half2*)&Oa[(size_t)(gr0 + 8) * DMODEL + col] =
            __floats2half2_rn(oA[nt][2] * inv1, oA[nt][3] * inv1);
    }
}

// ---------------------------------------------------------------------------
// RMSNorm: out exact fp32, outH half
// ---------------------------------------------------------------------------
__global__ __launch_bounds__(256) void rmsnorm_k(const float* __restrict__ x,
                                                 const float* __restrict__ g,
                                                 float* __restrict__ out,
                                                 __half* __restrict__ outH)
{
    int row = blockIdx.x;
    int tid = threadIdx.x;
    const float4* xr4 = (const float4*)(x + (size_t)row * DMODEL);
    const float4* g4  = (const float4*)g;

    float4 a = xr4[tid];
    float4 b = xr4[tid + 256];
    float s = a.x*a.x + a.y*a.y + a.z*a.z + a.w*a.w
            + b.x*b.x + b.y*b.y + b.z*b.z + b.w*b.w;
    #pragma unroll
    for (int off = 16; off > 0; off >>= 1) s += __shfl_xor_sync(0xffffffffu, s, off);

    __shared__ float red[8];
    __shared__ float inv_s;
    int wid = tid >> 5, lane = tid & 31;
    if (lane == 0) red[wid] = s;
    __syncthreads();
    if (tid == 0) {
        float t = 0.f;
        #pragma unroll
        for (int w = 0; w < 8; w++) t += red[w];
        inv_s = rsqrtf(t / (float)DMODEL + 1e-5f);
    }
    __syncthreads();
    float inv = inv_s;

    float4 ga = g4[tid], gb = g4[tid + 256];
    float4 ra, rb;
    ra.x = a.x*ga.x*inv; ra.y = a.y*ga.y*inv; ra.z = a.z*ga.z*inv; ra.w = a.w*ga.w*inv;
    rb.x = b.x*gb.x*inv; rb.y = b.y*gb.y*inv; rb.z = b.z*gb.z*inv; rb.w = b.w*gb.w*inv;
    ((float4*)(out + (size_t)row * DMODEL))[tid] = ra;
    ((float4*)(out + (size_t)row * DMODEL))[tid + 256] = rb;

    __half2* oh = (__half2*)(outH + (size_t)row * DMODEL);
    oh[tid * 2]       = __floats2half2_rn(ra.x, ra.y);
    oh[tid * 2 + 1]   = __floats2half2_rn(ra.z, ra.w);
    oh[(tid + 256) * 2]     = __floats2half2_rn(rb.x, rb.y);
    oh[(tid + 256) * 2 + 1] = __floats2half2_rn(rb.z, rb.w);
}

// ---------------------------------------------------------------------------
// kernel_launch
// ---------------------------------------------------------------------------
extern "C" void kernel_launch(void* const* d_in, const int* in_sizes, int n_in,
                              void* d_out, int out_size)
{
    (void)in_sizes; (void)n_in; (void)out_size;
    const float* x  = (const float*)d_in[0];
    const float* g1 = (const float*)d_in[1];
    const float* wq = (const float*)d_in[2];
    const float* wk = (const float*)d_in[3];
    const float* wv = (const float*)d_in[4];
    const float* wo = (const float*)d_in[5];
    const float* g2 = (const float*)d_in[6];
    const float* wg = (const float*)d_in[7];
    const float* wu = (const float*)d_in[8];
    const float* wd = (const float*)d_in[9];
    float* out = (float*)d_out;

    float *xn, *qkv, *h2, *h3, *gate, *rt;
    __half *xnh, *h3h, *atth, *gbh, *wqkvT, *woT, *wguT, *wdT;
    cudaGetSymbolAddress((void**)&xn,    g_xn);
    cudaGetSymbolAddress((void**)&qkv,   g_qkv);
    cudaGetSymbolAddress((void**)&h2,    g_h2);
    cudaGetSymbolAddress((void**)&h3,    g_h3);
    cudaGetSymbolAddress((void**)&gate,  g_gate);
    cudaGetSymbolAddress((void**)&rt,    g_rt);
    cudaGetSymbolAddress((void**)&xnh,   g_xnh);
    cudaGetSymbolAddress((void**)&h3h,   g_h3h);
    cudaGetSymbolAddress((void**)&atth,  g_atth);
    cudaGetSymbolAddress((void**)&gbh,   g_gbh);
    cudaGetSymbolAddress((void**)&wqkvT, g_wqkvT);
    cudaGetSymbolAddress((void**)&woT,   g_woT);
    cudaGetSymbolAddress((void**)&wguT,  g_wguT);
    cudaGetSymbolAddress((void**)&wdT,   g_wdT);

    cudaFuncSetAttribute(tgemm_k,   cudaFuncAttributeMaxDynamicSharedMemorySize, GSM_TOTAL);
    cudaFuncSetAttribute(attn_tc_k, cudaFuncAttributeMaxDynamicSharedMemorySize, ATT_SMEM_BYTES);

    dim3 tb(32, 8);
    // fused transposed half weights
    transpose_h_k<<<dim3(DMODEL/32, DMODEL/32), tb>>>(wq, wqkvT,                          DMODEL, DMODEL);
    transpose_h_k<<<dim3(512/32,    DMODEL/32), tb>>>(wk, wqkvT + (size_t)2048*DMODEL,    DMODEL, 512);
    transpose_h_k<<<dim3(512/32,    DMODEL/32), tb>>>(wv, wqkvT + (size_t)2560*DMODEL,    DMODEL, 512);
    transpose_h_k<<<dim3(DMODEL/32, DMODEL/32), tb>>>(wo, woT,                            DMODEL, DMODEL);
    transpose_h_k<<<dim3(FF/32,     DMODEL/32), tb>>>(wg, wguT,                           DMODEL, FF);
    transpose_h_k<<<dim3(FF/32,     DMODEL/32), tb>>>(wu, wguT + (size_t)FF*DMODEL,       DMODEL, FF);
    transpose_h_k<<<dim3(DMODEL/32, FF/32),     tb>>>(wd, wdT,                            FF, DMODEL);

    // rope table + h1 = rmsnorm(x, g1)
    rope_table_k<<<T_LEN * 32 / 256, 256>>>(rt);
    rmsnorm_k<<<T_LEN, 256>>>(x, g1, xn, xnh);

    // qkv = h1h @ [wq|wk|wv] (rope fused) -> fp32
    tgemm_k<<<dim3(QKV_N/256, T_LEN/128), 256, GSM_TOTAL>>>(
        xnh, wqkvT, qkv, T_LEN, QKV_N, DMODEL, nullptr, nullptr, 1, rt);

    attn_tc_k<<<dim3(T_LEN/64, NHEAD), 128, ATT_SMEM_BYTES>>>(qkv, atth);

    // h2 = h1 + att @ wo
    tgemm_k<<<dim3(DMODEL/256, T_LEN/128), 256, GSM_TOTAL>>>(
        atth, woT, h2, T_LEN, DMODEL, DMODEL, xn, nullptr, 0, nullptr);

    rmsnorm_k<<<T_LEN, 256>>>(h2, g2, h3, h3h);

    // gate = h3h @ wg -> fp32
    tgemm_k<<<dim3(FF/256, T_LEN/128), 256, GSM_TOTAL>>>(
        h3h, wguT, gate, T_LEN, FF, DMODEL, nullptr, nullptr, 0, nullptr);

    // gbh = half(silu(gate) * (h3h @ wu))
    tgemm_k<<<dim3(FF/256, T_LEN/128), 256, GSM_TOTAL>>>(
        h3h, wguT + (size_t)FF*DMODEL, gbh, T_LEN, FF, DMODEL, nullptr, nullptr, 2, gate);

    // out = gbh @ wd + h3 + x
    tgemm_k<<<dim3(DMODEL/256, T_LEN/128), 256, GSM_TOTAL>>>(
        gbh, wdT, out, T_LEN, DMODEL, FF, h3, x, 0, nullptr);
}

// round 16
// speedup vs baseline: 1.8060x; 1.0154x over previous
#include <cuda_runtime.h>
#include <cuda_fp16.h>
#include <cstdint>
#include <cstddef>

// ---------------------------------------------------------------------------
// LlamaDecoderLayer fp32. All GEMMs + attention via mma.sync m16n8k16 fp16
// (fp32 accumulate). Weights pre-transposed+converted to half WT[N][K].
// T=2048, D=2048, NH=32, NKV=8, HD=64, FF=8192.
// ---------------------------------------------------------------------------

#define T_LEN 2048
#define DMODEL 2048
#define NHEAD 32
#define NKV 8
#define HD 64
#define FF 8192
#define QKV_N 3072

// ---- scratch -------------------------------------------------------------
__device__ float  g_xn  [T_LEN * DMODEL];      // h1 exact (residual)
__device__ float  g_h2  [T_LEN * DMODEL];
__device__ float  g_h3  [T_LEN * DMODEL];      // exact (residual)
__device__ float  g_gate[T_LEN * FF];          // h3h @ wg (raw fp32)
__device__ float  g_rt  [T_LEN * 64];          // rope table
__device__ __half g_qkvh[T_LEN * QKV_N];       // qkv (rope applied), half
__device__ __half g_xnh [T_LEN * DMODEL];      // h1, half (GEMM A)
__device__ __half g_h3h [T_LEN * DMODEL];      // h3, half (GEMM A)
__device__ __half g_atth[T_LEN * DMODEL];      // attention out, half
__device__ __half g_gbh [T_LEN * FF];          // silu(gate)*up, half
// transposed half weights: WT[n][k] = (half)W[k][n]
__device__ __half g_wqkvT[QKV_N * DMODEL];
__device__ __half g_woT  [DMODEL * DMODEL];
__device__ __half g_wguT [2 * FF * DMODEL];
__device__ __half g_wdT  [DMODEL * FF];

// ---------------------------------------------------------------------------
// helpers
// ---------------------------------------------------------------------------
__device__ __forceinline__ uint32_t smem_u32(const void* p) {
    uint32_t a;
    asm("{ .reg .u64 t; cvta.to.shared.u64 t, %1; cvt.u32.u64 %0, t; }" : "=r"(a) : "l"(p));
    return a;
}
#define CP16(sm_addr, gptr) \
    asm volatile("cp.async.cg.shared.global [%0], [%1], 16;" :: "r"(sm_addr), "l"(gptr))
#define CP_COMMIT() asm volatile("cp.async.commit_group;")
#define CP_WAIT1()  asm volatile("cp.async.wait_group 1;")

// fp16 mma, fp32 accumulate
__device__ __forceinline__ void mma_h(float* c, const uint32_t* a, uint32_t b0, uint32_t b1) {
    asm volatile("mma.sync.aligned.m16n8k16.row.col.f32.f16.f16.f32 "
                 "{%0,%1,%2,%3}, {%4,%5,%6,%7}, {%8,%9}, {%0,%1,%2,%3};"
                 : "+f"(c[0]), "+f"(c[1]), "+f"(c[2]), "+f"(c[3])
                 : "r"(a[0]), "r"(a[1]), "r"(a[2]), "r"(a[3]), "r"(b0), "r"(b1));
}

// ---------------------------------------------------------------------------
// rope table: row t, d=0..31 -> (cos, sin)
// ---------------------------------------------------------------------------
__global__ __launch_bounds__(256) void rope_table_k(float* __restrict__ rt)
{
    int i = blockIdx.x * blockDim.x + threadIdx.x;
    int t = i >> 5, d = i & 31;
    double freq = exp((double)(-2.0 * d / 64.0) * 9.210340371976184);
    double si, co;
    sincos(freq * (double)t, &si, &co);
    ((float2*)rt)[i] = make_float2((float)co, (float)si);
}

// ---------------------------------------------------------------------------
// Weight transpose + half convert: W[K,N] fp32 -> WT[N,K] half
// ---------------------------------------------------------------------------
__global__ __launch_bounds__(256) void transpose_h_k(const float* __restrict__ W,
                                                     __half* __restrict__ WT,
                                                     int K, int N)
{
    __shared__ float t[32][33];
    int n0 = blockIdx.x * 32, k0 = blockIdx.y * 32;
    int tx = threadIdx.x, ty = threadIdx.y;
    #pragma unroll
    for (int i = 0; i < 32; i += 8)
        t[ty + i][tx] = W[(size_t)(k0 + ty + i) * N + n0 + tx];
    __syncthreads();
    #pragma unroll
    for (int i = 0; i < 32; i += 8)
        WT[(size_t)(n0 + ty + i) * K + k0 + tx] = __float2half_rn(t[tx][ty + i]);
}

// ---------------------------------------------------------------------------
// fp16 tensor-core GEMM: C[M,Nc] = A[M,K] @ WT[N,K]^T (+add0 +add1)
// CTA 128x256, BK=16, 3-stage cp.async, 8 warps x (64x64).
// epi: 0=none(C fp32), 1=rope(C half), 2=silu(C half, epi_src=gate fp32)
// ---------------------------------------------------------------------------
#define AS 24                                   // halfs per A smem row (16+8)
#define A_BYTES (128 * AS * 2)                  // 6144
#define B_BYTES (256 * AS * 2)                  // 12288
#define STG_B   (A_BYTES + B_BYTES)             // 18432
#define GSM_TOTAL (3 * STG_B)                   // 55296

__global__ __launch_bounds__(256, 1) void tgemm_k(const __half* __restrict__ A,
                                                  const __half* __restrict__ BT,
                                                  void* __restrict__ Cv,
                                                  int M, int Nc, int K,
                                                  const float* __restrict__ add0,
                                                  const float* __restrict__ add1,
                                                  int epi,
                                                  const float* __restrict__ epi_src)
{
    extern __shared__ char sm[];
    const uint32_t smb = smem_u32(sm);
    const int tid = threadIdx.x;
    const int wid = tid >> 5, lane = tid & 31;
    const int warp_m = wid & 1;
    const int warp_n = wid >> 1;
    const int brow = blockIdx.y * 128;
    const int bcol = blockIdx.x * 256;

    const __half* aG = A + (size_t)(brow + (tid >> 1)) * K + (tid & 1) * 8;
    const uint32_t sA0 = smb + (tid >> 1) * (AS * 2) + (tid & 1) * 16;
    const __half* bG = BT + (size_t)(bcol + (tid >> 1)) * K + (tid & 1) * 8;
    const uint32_t sB0 = smb + A_BYTES + (tid >> 1) * (AS * 2) + (tid & 1) * 16;
    const size_t bRowStride = (size_t)128 * K;
    const uint32_t sBRow = 128 * (AS * 2);

    float c[4][8][4];
    #pragma unroll
    for (int mi = 0; mi < 4; mi++)
        #pragma unroll
        for (int ni = 0; ni < 8; ni++)
            #pragma unroll
            for (int j = 0; j < 4; j++) c[mi][ni][j] = 0.f;

    const int nk = K >> 4;

    #pragma unroll
    for (int p = 0; p < 2; p++) {
        const __half* a0 = aG + p * 16;
        const __half* b0 = bG + p * 16;
        uint32_t sa = sA0 + p * STG_B;
        uint32_t sb = sB0 + p * STG_B;
        CP16(sa, a0);
        CP16(sb, b0);
        CP16(sb + sBRow, b0 + bRowStride);
        CP_COMMIT();
    }

    const int r1 = lane >> 2, cq = lane & 3;
    const uint32_t lm_off =
        (uint32_t)(warp_m * 64 + (lane & 15)) * (AS * 2) + (uint32_t)(lane >> 4) * 16;

    for (int kt = 0; kt < nk; kt++) {
        CP_WAIT1();
        __syncthreads();

        if (kt + 2 < nk) {
            int st = (kt + 2) % 3;
            const __half* a0 = aG + (size_t)(kt + 2) * 16;
            const __half* b0 = bG + (size_t)(kt + 2) * 16;
            uint32_t sa = sA0 + st * STG_B;
            uint32_t sb = sB0 + st * STG_B;
            CP16(sa, a0);
            CP16(sb, b0);
            CP16(sb + sBRow, b0 + bRowStride);
        }
        CP_COMMIT();

        const uint32_t stg = smb + (kt % 3) * STG_B;
        const __half* Bs = (const __half*)(sm + (kt % 3) * STG_B + A_BYTES);

        uint32_t a[4][4];
        const uint32_t abase = stg + lm_off;
        #pragma unroll
        for (int mi = 0; mi < 4; mi++) {
            asm volatile("ldmatrix.sync.aligned.m8n8.x4.shared.b16 {%0,%1,%2,%3}, [%4];"
                         : "=r"(a[mi][0]), "=r"(a[mi][1]),
                           "=r"(a[mi][2]), "=r"(a[mi][3])
                         : "r"(abase + (uint32_t)(mi * 16 * AS * 2)));
        }
        const __half* bp = Bs + (warp_n * 64 + r1) * AS + 2 * cq;
        uint32_t b0[8], b1[8];
        #pragma unroll
        for (int ni = 0; ni < 8; ni++) {
            b0[ni] = *(const uint32_t*)(bp + ni * 8 * AS);
            b1[ni] = *(const uint32_t*)(bp + ni * 8 * AS + 8);
        }
        #pragma unroll
        for (int mi = 0; mi < 4; mi++)
            #pragma unroll
            for (int ni = 0; ni < 8; ni++)
                mma_h(c[mi][ni], a[mi], b0[ni], b1[ni]);
    }

    // ---- epilogue ----
    float* C = (float*)Cv;
    __half* Ch = (__half*)Cv;
    #pragma unroll
    for (int mi = 0; mi < 4; mi++) {
        #pragma unroll
        for (int part = 0; part < 2; part++) {
            int r = brow + warp_m * 64 + mi * 16 + r1 + part * 8;
            size_t rowbase = (size_t)r * Nc;
            #pragma unroll
            for (int ni = 0; ni < 8; ni++) {
                int col = bcol + warp_n * 64 + ni * 8 + cq * 2;
                float2 v = make_float2(c[mi][ni][part * 2], c[mi][ni][part * 2 + 1]);
                if (epi == 1) {         // rope (q/k cols) -> half C
                    if (col < 2560) {
                        int dp = (col & 63) >> 1;
                        float2 cssn = ((const float2*)epi_src)[r * 32 + dp];
                        float x1 = v.x, x2 = v.y;
                        v.x = x1 * cssn.x - x2 * cssn.y;
                        v.y = x2 * cssn.x + x1 * cssn.y;
                    }
                    *(__half2*)(Ch + rowbase + col) = __floats2half2_rn(v.x, v.y);
                    continue;
                } else if (epi == 2) {  // v = up; silu(gate)*up -> half C
                    const float2 gt = *(const float2*)&epi_src[rowbase + col];
                    float sx = gt.x / (1.f + __expf(-gt.x)) * v.x;
                    float sy = gt.y / (1.f + __expf(-gt.y)) * v.y;
                    *(__half2*)(Ch + rowbase + col) = __floats2half2_rn(sx, sy);
                    continue;
                }
                if (add0) { const float2 a2 = *(const float2*)&add0[rowbase + col];
                            v.x += a2.x; v.y += a2.y; }
                if (add1) { const float2 a2 = *(const float2*)&add1[rowbase + col];
                            v.x += a2.x; v.y += a2.y; }
                *(float2*)&C[rowbase + col] = v;
            }
        }
    }
}

// ---------------------------------------------------------------------------
// fp16 tensor-core flash attention (causal GQA). Block = 64 q rows x 1 head,
// 4 warps, mma m16n8k16. QKV input half (rope already applied). Output half.
// smem halfs: qsm [64][72] | ksm [64][72] | vsmT [64 d][72 kv] | psm 4x[16][72]
// ---------------------------------------------------------------------------
#define ATT_SMEM_BYTES (18432 * 2)

__global__ __launch_bounds__(128) void attn_tc_k(const __half* __restrict__ QKV,
                                                 __half* __restrict__ Oa)
{
    extern __shared__ __half sh[];
    __half* qsm  = sh;               // [64][72]
    __half* ksm  = sh + 4608;        // [64][72]
    __half* vsmT = sh + 9216;        // [64 d][72 kv]
    __half* psm  = sh + 13824;       // [4][16][72]

    const int tid = threadIdx.x;
    const int w = tid >> 5, lane = tid & 31;
    const int r1 = lane >> 2, cq = lane & 3;
    const int qt = blockIdx.x, h = blockIdx.y;
    const int kvh = h >> 2;

    // ---- load Q tile (half, 16B chunks) ----
    {
        const __half* qb = QKV + (size_t)(qt * 64) * QKV_N + h * HD;
        for (int t = tid; t < 512; t += 128) {
            int i = t >> 3, d8 = (t & 7) * 8;
            *(uint4*)(qsm + i * 72 + d8) = *(const uint4*)(qb + (size_t)i * QKV_N + d8);
        }
    }
    __syncthreads();

    // ---- Q fragments: 4 k16 steps x 4 regs ----
    uint32_t qf[4][4];
    {
        const __half* qp = qsm + (w * 16 + r1) * 72 + 2 * cq;
        #pragma unroll
        for (int kk = 0; kk < 4; kk++) {
            qf[kk][0] = *(const uint32_t*)(qp + kk * 16);
            qf[kk][1] = *(const uint32_t*)(qp + 8 * 72 + kk * 16);
            qf[kk][2] = *(const uint32_t*)(qp + kk * 16 + 8);
            qf[kk][3] = *(const uint32_t*)(qp + 8 * 72 + kk * 16 + 8);
        }
    }

    float oA[8][4];
    #pragma unroll
    for (int nt = 0; nt < 8; nt++)
        #pragma unroll
        for (int j = 0; j < 4; j++) oA[nt][j] = 0.f;
    float m0 = -1e30f, m1 = -1e30f, l0 = 0.f, l1 = 0.f;

    __half* pb = psm + w * 16 * 72;

    for (int jt = 0; jt <= qt; jt++) {
        __syncthreads();
        {
            const __half* kb = QKV + (size_t)(jt * 64) * QKV_N + DMODEL + kvh * HD;
            const __half* vb = kb + 512;
            for (int t = tid; t < 512; t += 128) {
                int i = t >> 3, d8 = (t & 7) * 8;
                *(uint4*)(ksm + i * 72 + d8) = *(const uint4*)(kb + (size_t)i * QKV_N + d8);
                uint4 raw = *(const uint4*)(vb + (size_t)i * QKV_N + d8);
                const __half* hp = (const __half*)&raw;
                #pragma unroll
                for (int j = 0; j < 8; j++) vsmT[(d8 + j) * 72 + i] = hp[j];
            }
        }
        __syncthreads();

        // ---- S = Q @ K^T ----
        float sA[8][4];
        #pragma unroll
        for (int nt = 0; nt < 8; nt++) {
            float acc[4] = {0.f, 0.f, 0.f, 0.f};
            const __half* kp = ksm + (nt * 8 + r1) * 72 + 2 * cq;
            #pragma unroll
            for (int kk = 0; kk < 4; kk++) {
                uint32_t b0 = *(const uint32_t*)(kp + kk * 16);
                uint32_t b1 = *(const uint32_t*)(kp + kk * 16 + 8);
                mma_h(acc, qf[kk], b0, b1);
            }
            sA[nt][0] = acc[0]; sA[nt][1] = acc[1];
            sA[nt][2] = acc[2]; sA[nt][3] = acc[3];
        }

        // ---- scale + causal mask + row max (fp32) ----
        float mn0 = m0, mn1 = m1;
        const int row0 = w * 16 + r1, row1 = row0 + 8;
        #pragma unroll
        for (int nt = 0; nt < 8; nt++) {
            #pragma unroll
            for (int j = 0; j < 4; j++) sA[nt][j] *= 0.125f;
            if (jt == qt) {
                int colb = nt * 8 + 2 * cq;
                if (colb     > row0) sA[nt][0] = -1e30f;
                if (colb + 1 > row0) sA[nt][1] = -1e30f;
                if (colb     > row1) sA[nt][2] = -1e30f;
                if (colb + 1 > row1) sA[nt][3] = -1e30f;
            }
            mn0 = fmaxf(mn0, fmaxf(sA[nt][0], sA[nt][1]));
            mn1 = fmaxf(mn1, fmaxf(sA[nt][2], sA[nt][3]));
        }
        mn0 = fmaxf(mn0, __shfl_xor_sync(0xffffffffu, mn0, 1));
        mn0 = fmaxf(mn0, __shfl_xor_sync(0xffffffffu, mn0, 2));
        mn1 = fmaxf(mn1, __shfl_xor_sync(0xffffffffu, mn1, 1));
        mn1 = fmaxf(mn1, __shfl_xor_sync(0xffffffffu, mn1, 2));

        float c0 = __expf(m0 - mn0), c1 = __expf(m1 - mn1);
        m0 = mn0; m1 = mn1;

        // ---- P = exp(S - m) rounded to half -> psm; partial sums ----
        float ls0 = 0.f, ls1 = 0.f;
        #pragma unroll
        for (int nt = 0; nt < 8; nt++) {
            __half2 hA = __floats2half2_rn(__expf(sA[nt][0] - mn0), __expf(sA[nt][1] - mn0));
            __half2 hB = __floats2half2_rn(__expf(sA[nt][2] - mn1), __expf(sA[nt][3] - mn1));
            float2 fA = __half22float2(hA), fB = __half22float2(hB);
            ls0 += fA.x + fA.y; ls1 += fB.x + fB.y;
            int cb = nt * 8 + 2 * cq;
            *(__half2*)(pb + r1 * 72 + cb)       = hA;
            *(__half2*)(pb + (r1 + 8) * 72 + cb) = hB;
        }
        ls0 += __shfl_xor_sync(0xffffffffu, ls0, 1);
        ls0 += __shfl_xor_sync(0xffffffffu, ls0, 2);
        ls1 += __shfl_xor_sync(0xffffffffu, ls1, 1);
        ls1 += __shfl_xor_sync(0xffffffffu, ls1, 2);
        l0 = l0 * c0 + ls0;
        l1 = l1 * c1 + ls1;

        // ---- rescale O ----
        #pragma unroll
        for (int nt = 0; nt < 8; nt++) {
            oA[nt][0] *= c0; oA[nt][1] *= c0;
            oA[nt][2] *= c1; oA[nt][3] *= c1;
        }
        __syncwarp();

        // ---- O += P @ V ----
        #pragma unroll
        for (int kk = 0; kk < 4; kk++) {
            uint32_t a[4];
            a[0] = *(const uint32_t*)(pb + r1 * 72 + kk * 16 + 2 * cq);
            a[1] = *(const uint32_t*)(pb + (r1 + 8) * 72 + kk * 16 + 2 * cq);
            a[2] = *(const uint32_t*)(pb + r1 * 72 + kk * 16 + 2 * cq + 8);
            a[3] = *(const uint32_t*)(pb + (r1 + 8) * 72 + kk * 16 + 2 * cq + 8);
            #pragma unroll
            for (int nt = 0; nt < 8; nt++) {
                const __half* vp = vsmT + (nt * 8 + r1) * 72 + kk * 16 + 2 * cq;
                uint32_t b0 = *(const uint32_t*)vp;
                uint32_t b1 = *(const uint32_t*)(vp + 8);
                mma_h(oA[nt], a, b0, b1);
            }
        }
    }

    // ---- epilogue ----
    float inv0 = 1.f / l0, inv1 = 1.f / l1;
    int gr0 = qt * 64 + w * 16 + r1;
    #pragma unroll
    for (int nt = 0; nt < 8; nt++) {
        int col = h * HD + nt * 8 + 2 * cq;
        *(__half2*)&Oa[(size_t)gr0 * DMODEL + col] =
            __floats2half2_rn(oA[nt][0] * inv0, oA[nt][1] * inv0);
        *(__half2*)&Oa[(size_t)(gr0 + 8) * DMODEL + col] =
            __floats2half2_rn(oA[nt][2] * inv1, oA[nt][3] * inv1);
    }
}

// ---------------------------------------------------------------------------
// RMSNorm: out exact fp32, outH half
// ---------------------------------------------------------------------------
__global__ __launch_bounds__(256) void rmsnorm_k(const float* __restrict__ x,
                                                 const float* __restrict__ g,
                                                 float* __restrict__ out,
                                                 __half* __restrict__ outH)
{
    int row = blockIdx.x;
    int tid = threadIdx.x;
    const float4* xr4 = (const float4*)(x + (size_t)row * DMODEL);
    const float4* g4  = (const float4*)g;

    float4 a = xr4[tid];
    float4 b = xr4[tid + 256];
    float s = a.x*a.x + a.y*a.y + a.z*a.z + a.w*a.w
            + b.x*b.x + b.y*b.y + b.z*b.z + b.w*b.w;
    #pragma unroll
    for (int off = 16; off > 0; off >>= 1) s += __shfl_xor_sync(0xffffffffu, s, off);

    __shared__ float red[8];
    __shared__ float inv_s;
    int wid = tid >> 5, lane = tid & 31;
    if (lane == 0) red[wid] = s;
    __syncthreads();
    if (tid == 0) {
        float t = 0.f;
        #pragma unroll
        for (int w = 0; w < 8; w++) t += red[w];
        inv_s = rsqrtf(t / (float)DMODEL + 1e-5f);
    }
    __syncthreads();
    float inv = inv_s;

    float4 ga = g4[tid], gb = g4[tid + 256];
    float4 ra, rb;
    ra.x = a.x*ga.x*inv; ra.y = a.y*ga.y*inv; ra.z = a.z*ga.z*inv; ra.w = a.w*ga.w*inv;
    rb.x = b.x*gb.x*inv; rb.y = b.y*gb.y*inv; rb.z = b.z*gb.z*inv; rb.w = b.w*gb.w*inv;
    ((float4*)(out + (size_t)row * DMODEL))[tid] = ra;
    ((float4*)(out + (size_t)row * DMODEL))[tid + 256] = rb;

    __half2* oh = (__half2*)(outH + (size_t)row * DMODEL);
    oh[tid * 2]       = __floats2half2_rn(ra.x, ra.y);
    oh[tid * 2 + 1]   = __floats2half2_rn(ra.z, ra.w);
    oh[(tid + 256) * 2]     = __floats2half2_rn(rb.x, rb.y);
    oh[(tid + 256) * 2 + 1] = __floats2half2_rn(rb.z, rb.w);
}

// ---------------------------------------------------------------------------
// kernel_launch
// ---------------------------------------------------------------------------
extern "C" void kernel_launch(void* const* d_in, const int* in_sizes, int n_in,
                              void* d_out, int out_size)
{
    (void)in_sizes; (void)n_in; (void)out_size;
    const float* x  = (const float*)d_in[0];
    const float* g1 = (const float*)d_in[1];
    const float* wq = (const float*)d_in[2];
    const float* wk = (const float*)d_in[3];
    const float* wv = (const float*)d_in[4];
    const float* wo = (const float*)d_in[5];
    const float* g2 = (const float*)d_in[6];
    const float* wg = (const float*)d_in[7];
    const float* wu = (const float*)d_in[8];
    const float* wd = (const float*)d_in[9];
    float* out = (float*)d_out;

    float *xn, *h2, *h3, *gate, *rt;
    __half *qkvh, *xnh, *h3h, *atth, *gbh, *wqkvT, *woT, *wguT, *wdT;
    cudaGetSymbolAddress((void**)&xn,    g_xn);
    cudaGetSymbolAddress((void**)&h2,    g_h2);
    cudaGetSymbolAddress((void**)&h3,    g_h3);
    cudaGetSymbolAddress((void**)&gate,  g_gate);
    cudaGetSymbolAddress((void**)&rt,    g_rt);
    cudaGetSymbolAddress((void**)&qkvh,  g_qkvh);
    cudaGetSymbolAddress((void**)&xnh,   g_xnh);
    cudaGetSymbolAddress((void**)&h3h,   g_h3h);
    cudaGetSymbolAddress((void**)&atth,  g_atth);
    cudaGetSymbolAddress((void**)&gbh,   g_gbh);
    cudaGetSymbolAddress((void**)&wqkvT, g_wqkvT);
    cudaGetSymbolAddress((void**)&woT,   g_woT);
    cudaGetSymbolAddress((void**)&wguT,  g_wguT);
    cudaGetSymbolAddress((void**)&wdT,   g_wdT);

    cudaFuncSetAttribute(tgemm_k,   cudaFuncAttributeMaxDynamicSharedMemorySize, GSM_TOTAL);
    cudaFuncSetAttribute(attn_tc_k, cudaFuncAttributeMaxDynamicSharedMemorySize, ATT_SMEM_BYTES);

    dim3 tb(32, 8);
    // fused transposed half weights
    transpose_h_k<<<dim3(DMODEL/32, DMODEL/32), tb>>>(wq, wqkvT,                          DMODEL, DMODEL);
    transpose_h_k<<<dim3(512/32,    DMODEL/32), tb>>>(wk, wqkvT + (size_t)2048*DMODEL,    DMODEL, 512);
    transpose_h_k<<<dim3(512/32,    DMODEL/32), tb>>>(wv, wqkvT + (size_t)2560*DMODEL,    DMODEL, 512);
    transpose_h_k<<<dim3(DMODEL/32, DMODEL/32), tb>>>(wo, woT,                            DMODEL, DMODEL);
    transpose_h_k<<<dim3(FF/32,     DMODEL/32), tb>>>(wg, wguT,                           DMODEL, FF);
    transpose_h_k<<<dim3(FF/32,     DMODEL/32), tb>>>(wu, wguT + (size_t)FF*DMODEL,       DMODEL, FF);
    transpose_h_k<<<dim3(DMODEL/32, FF/32),     tb>>>(wd, wdT,                            FF, DMODEL);

    // rope table + h1 = rmsnorm(x, g1)
    rope_table_k<<<T_LEN * 32 / 256, 256>>>(rt);
    rmsnorm_k<<<T_LEN, 256>>>(x, g1, xn, xnh);

    // qkvh = half(rope(h1h @ [wq|wk|wv]))
    tgemm_k<<<dim3(QKV_N/256, T_LEN/128), 256, GSM_TOTAL>>>(
        xnh, wqkvT, qkvh, T_LEN, QKV_N, DMODEL, nullptr, nullptr, 1, rt);

    attn_tc_k<<<dim3(T_LEN/64, NHEAD), 128, ATT_SMEM_BYTES>>>(qkvh, atth);

    // h2 = h1 + att @ wo
    tgemm_k<<<dim3(DMODEL/256, T_LEN/128), 256, GSM_TOTAL>>>(
        atth, woT, h2, T_LEN, DMODEL, DMODEL, xn, nullptr, 0, nullptr);

    rmsnorm_k<<<T_LEN, 256>>>(h2, g2, h3, h3h);

    // gate = h3h @ wg -> fp32
    tgemm_k<<<dim3(FF/256, T_LEN/128), 256, GSM_TOTAL>>>(
        h3h, wguT, gate, T_LEN, FF, DMODEL, nullptr, nullptr, 0, nullptr);

    // gbh = half(silu(gate) * (h3h @ wu))
    tgemm_k<<<dim3(FF/256, T_LEN/128), 256, GSM_TOTAL>>>(
        h3h, wguT + (size_t)FF*DMODEL, gbh, T_LEN, FF, DMODEL, nullptr, nullptr, 2, gate);

    // out = gbh @ wd + h3 + x
    tgemm_k<<<dim3(DMODEL/256, T_LEN/128), 256, GSM_TOTAL>>>(
        gbh, wdT, out, T_LEN, DMODEL, FF, h3, x, 0, nullptr);
}